// round 2
// baseline (speedup 1.0000x reference)
#include <cuda_runtime.h>

// SigmoidFlow: B=2048, D=512, NDIM=16
// out[0 .. B*D) = xnew ; out[B*D .. B*D+B) = logdet
//
// Identities used:
//  logsumexp_k(log_softmax(wl)+logsig(pre)+logsig(-pre)+log a)
//      = log( sum_k ew_k * a_k * t_k * g_k^2 ) - log(W)
//  with t=exp(-pre), g=1/(1+t)=sigm, ew=exp(wl), W=sum ew.
//  Single-rcp trick: g_k = cofactor_k(1+t) / prod(1+t)  -> 1 MUFU.RCP per 4 comps.
//  xnew  = log(N1) - log(N2),   N1=(1-d)*S + (d/2)*W,  N2=(1-d)*(W-S) + (d/2)*W
//  ldterm= log(D*W) - log(N1) - log(N2) + log(1-d)     (all 1/W factors cancel)

#define TPB 512

__device__ __forceinline__ float fast_rcp(float v) {
    float r; asm("rcp.approx.f32 %0, %1;" : "=f"(r) : "f"(v)); return r;
}

struct Tile { float4 av, bv, wv; float xv; };

__device__ __forceinline__ void sf_compute(const Tile& T, float xv,
                                           float& Wl, float& Sl, float& Dl)
{
    float a_[4] = {T.av.x, T.av.y, T.av.z, T.av.w};
    float b_[4] = {T.bv.x, T.bv.y, T.bv.z, T.bv.w};
    float wl[4] = {T.wv.x, T.wv.y, T.wv.z, T.wv.w};

    float asp[4], t[4], onet[4], ew[4];
    #pragma unroll
    for (int j = 0; j < 4; ++j) {
        float ea  = __expf(a_[j]);
        asp[j]    = __logf(1.0f + ea);          // softplus
        float pre = fmaf(asp[j], xv, b_[j]);
        t[j]      = __expf(-pre);
        onet[j]   = 1.0f + t[j];
        ew[j]     = __expf(wl[j]);
    }
    float p01 = onet[0] * onet[1];
    float p23 = onet[2] * onet[3];
    float P   = p01 * p23;
    float iP  = fast_rcp(P);
    float h0  = (onet[1] * p23) * iP;           // = 1/(1+t0)
    float h1  = (onet[0] * p23) * iP;
    float h2  = (p01 * onet[3]) * iP;
    float h3  = (p01 * onet[2]) * iP;

    Wl = ((ew[0] + ew[1]) + (ew[2] + ew[3]));
    Sl = fmaf(ew[3], h3, fmaf(ew[2], h2, fmaf(ew[1], h1, ew[0] * h0)));
    float d0 = (ew[0] * asp[0]) * (t[0] * h0 * h0);
    float d1 = (ew[1] * asp[1]) * (t[1] * h1 * h1);
    float d2 = (ew[2] * asp[2]) * (t[2] * h2 * h2);
    float d3 = (ew[3] * asp[3]) * (t[3] * h3 * h3);
    Dl = (d0 + d1) + (d2 + d3);
}

template<int NITER>
__global__ __launch_bounds__(TPB, 2)
void sf_kernel(const float* __restrict__ x,
               const float* __restrict__ logdet_in,
               const float* __restrict__ dsp,
               float* __restrict__ out,
               int B, int D)
{
    const int b    = blockIdx.x;
    const int tid  = threadIdx.x;
    const int lane = tid & 31;
    const int wid  = tid >> 5;
    const int q    = lane & 3;
    const int e_in_block = wid * 8 + (lane >> 2);   // 0..127

    const float ONE_MD = 1.0f - 1e-6f;
    const float HALF_D = 0.5e-6f;
    const float LOG1MD = -1.0000005e-6f;

    __shared__ float s_part[TPB / 32];

    const float4* base = (const float4*)(dsp + ((long long)b * D + e_in_block) * 48);
    const float*  xb   = x + (long long)b * D + e_in_block;

    float acc = 0.0f;

    Tile cur;
    cur.av = __ldcs(base + q);
    cur.bv = __ldcs(base + 4 + q);
    cur.wv = __ldcs(base + 8 + q);
    cur.xv = __ldcs(xb);

    #pragma unroll
    for (int it = 0; it < NITER; ++it) {
        Tile nxt = cur;
        if (it + 1 < NITER) {
            const float4* pn = base + (it + 1) * 1536;   // 128 elems * 12 float4
            nxt.av = __ldcs(pn + q);
            nxt.bv = __ldcs(pn + 4 + q);
            nxt.wv = __ldcs(pn + 8 + q);
            nxt.xv = __ldcs(xb + (it + 1) * 128);
        }

        float Wl, Sl, Dl;
        sf_compute(cur, cur.xv, Wl, Sl, Dl);

        // reduce (W,S,D) across the 4-lane group
        Wl += __shfl_xor_sync(0xffffffffu, Wl, 1);
        Sl += __shfl_xor_sync(0xffffffffu, Sl, 1);
        Dl += __shfl_xor_sync(0xffffffffu, Dl, 1);
        Wl += __shfl_xor_sync(0xffffffffu, Wl, 2);
        Sl += __shfl_xor_sync(0xffffffffu, Sl, 2);
        Dl += __shfl_xor_sync(0xffffffffu, Dl, 2);

        const float hw = HALF_D * Wl;
        const float N1 = fmaf(ONE_MD, Sl, hw);
        const float N2 = fmaf(ONE_MD, Wl - Sl, hw);
        const float l1 = __logf(N1);
        const float l2 = __logf(N2);
        const float l3 = __logf(Dl * Wl);

        const long long idx = (long long)b * D + it * 128 + e_in_block;
        if (q == 0) __stcs(out + idx, l1 - l2);     // xnew
        acc += l3 - l1 - l2 + LOG1MD;               // replicated on 4 lanes

        cur = nxt;
    }

    // warp + block reduction (each element counted 4x -> scale 0.25)
    #pragma unroll
    for (int m = 16; m >= 1; m >>= 1)
        acc += __shfl_xor_sync(0xffffffffu, acc, m);
    if (lane == 0) s_part[wid] = acc;
    __syncthreads();

    if (wid == 0) {
        float v = (lane < (TPB / 32)) ? s_part[lane] : 0.0f;
        #pragma unroll
        for (int m = 8; m >= 1; m >>= 1)
            v += __shfl_xor_sync(0xffffffffu, v, m);
        if (lane == 0)
            out[(long long)B * D + b] = 0.25f * v + __ldg(logdet_in + b);
    }
}

// Generic fallback for unexpected D (guarded loop, same math).
__global__ __launch_bounds__(TPB)
void sf_kernel_gen(const float* __restrict__ x,
                   const float* __restrict__ logdet_in,
                   const float* __restrict__ dsp,
                   float* __restrict__ out,
                   int B, int D)
{
    const int b    = blockIdx.x;
    const int tid  = threadIdx.x;
    const int lane = tid & 31;
    const int wid  = tid >> 5;
    const int q    = lane & 3;
    const int e_in_block = wid * 8 + (lane >> 2);

    const float ONE_MD = 1.0f - 1e-6f;
    const float HALF_D = 0.5e-6f;
    const float LOG1MD = -1.0000005e-6f;

    __shared__ float s_part[TPB / 32];
    float acc = 0.0f;

    const int niter = (D + 127) / 128;
    for (int it = 0; it < niter; ++it) {
        const int d = it * 128 + e_in_block;
        if (d < D) {
            const long long idx = (long long)b * D + d;
            Tile T;
            const float4* p = (const float4*)(dsp + idx * 48);
            T.av = __ldcs(p + q); T.bv = __ldcs(p + 4 + q); T.wv = __ldcs(p + 8 + q);
            float xv = __ldcs(x + idx);

            float Wl, Sl, Dl;
            sf_compute(T, xv, Wl, Sl, Dl);

            Wl += __shfl_xor_sync(0xffffffffu, Wl, 1);
            Sl += __shfl_xor_sync(0xffffffffu, Sl, 1);
            Dl += __shfl_xor_sync(0xffffffffu, Dl, 1);
            Wl += __shfl_xor_sync(0xffffffffu, Wl, 2);
            Sl += __shfl_xor_sync(0xffffffffu, Sl, 2);
            Dl += __shfl_xor_sync(0xffffffffu, Dl, 2);

            const float hw = HALF_D * Wl;
            const float N1 = fmaf(ONE_MD, Sl, hw);
            const float N2 = fmaf(ONE_MD, Wl - Sl, hw);
            const float l1 = __logf(N1);
            const float l2 = __logf(N2);
            const float l3 = __logf(Dl * Wl);

            if (q == 0) __stcs(out + idx, l1 - l2);
            acc += l3 - l1 - l2 + LOG1MD;
        }
    }

    #pragma unroll
    for (int m = 16; m >= 1; m >>= 1)
        acc += __shfl_xor_sync(0xffffffffu, acc, m);
    if (lane == 0) s_part[wid] = acc;
    __syncthreads();

    if (wid == 0) {
        float v = (lane < (TPB / 32)) ? s_part[lane] : 0.0f;
        #pragma unroll
        for (int m = 8; m >= 1; m >>= 1)
            v += __shfl_xor_sync(0xffffffffu, v, m);
        if (lane == 0)
            out[(long long)B * D + b] = 0.25f * v + __ldg(logdet_in + b);
    }
}

extern "C" void kernel_launch(void* const* d_in, const int* in_sizes, int n_in,
                              void* d_out, int out_size)
{
    const float* x   = (const float*)d_in[0];
    const float* ld  = (const float*)d_in[1];
    const float* dsp = (const float*)d_in[2];
    float* out = (float*)d_out;

    const int B = in_sizes[1];
    const int D = in_sizes[0] / B;

    if (D == 512)
        sf_kernel<4><<<B, TPB>>>(x, ld, dsp, out, B, D);
    else
        sf_kernel_gen<<<B, TPB>>>(x, ld, dsp, out, B, D);
}